// round 2
// baseline (speedup 1.0000x reference)
#include <cuda_runtime.h>

// Problem constants
#define NM      31
#define NPLANE  (NM*NM)        // 961
#define NK      (NM*NM*NM)     // 29791
#define NB      8
#define NPTS    3000
#define NCH     4
#define NBW     12
#define NXH     16             // half-space planes nx = 0..15
#define NSPLIT  3
#define JCHUNK  (NPTS/NSPLIT)  // 1000
#define TWO_PI_L 0.628318530717958647692f
#define HALF_L   5.0f
#define INV2V    (1.0f/2000.0f)

typedef unsigned long long u64;

// Scratch (static device globals; allocation-free per harness rules)
__device__ float2 g_E[NB*NPTS*3*NM];                 // [pidx][dim][n]
__device__ float2 g_Fp[NSPLIT*NB*NCH*NXH*NPLANE];    // partial structure factors
__device__ float2 g_F[NB*NCH*NXH*NPLANE];            // mult-folded structure factor
__device__ float  g_mult[NK];
__device__ float  g_diag;

__device__ __forceinline__ float2 cmul(float2 a, float2 b) {
    return make_float2(a.x*b.x - a.y*b.y, a.x*b.y + a.y*b.x);
}
__device__ __forceinline__ u64 pk(float x, float y) {
    u64 r; asm("mov.b64 %0,{%1,%2};" : "=l"(r) : "f"(x), "f"(y)); return r;
}
__device__ __forceinline__ float2 upk(u64 v) {
    float2 f; asm("mov.b64 {%0,%1},%2;" : "=f"(f.x), "=f"(f.y) : "l"(v)); return f;
}
__device__ __forceinline__ u64 ffma2(u64 a, u64 b, u64 c) {
    u64 d; asm("fma.rn.f32x2 %0,%1,%2,%3;" : "=l"(d) : "l"(a), "l"(b), "l"(c)); return d;
}
__device__ __forceinline__ u64 fmul2(u64 a, u64 b) {
    u64 d; asm("mul.rn.f32x2 %0,%1,%2;" : "=l"(d) : "l"(a), "l"(b)); return d;
}

// ---------------------------------------------------------------------------
// 1) mult(k)
// ---------------------------------------------------------------------------
__global__ void mult_kernel(const float* __restrict__ shift,
                            const float* __restrict__ amp) {
    int i = blockIdx.x * blockDim.x + threadIdx.x;
    if (i >= NK) return;
    int ix = i / NPLANE;
    int r  = i - ix * NPLANE;
    int iy = r / NM;
    int iz = r - iy * NM;
    float kx = TWO_PI_L * (float)(ix - 15);
    float ky = TWO_PI_L * (float)(iy - 15);
    float kz = TWO_PI_L * (float)(iz - 15);
    float k2 = kx*kx + ky*ky + kz*kz;
    float m = 0.0f;
#pragma unroll
    for (int b = 0; b < NBW; b++) {
        m += amp[b] * __expf(-k2 * __expf(2.0f * shift[b]));
    }
    if (k2 == 0.0f) m = 0.0f;
    g_mult[i] = m;
}

// ---------------------------------------------------------------------------
// 2) diag_sum
// ---------------------------------------------------------------------------
__global__ void diag_kernel() {
    __shared__ float sh[1024];
    int tid = threadIdx.x;
    float s = 0.0f;
    for (int i = tid; i < NK; i += 1024) s += g_mult[i];
    sh[tid] = s;
    __syncthreads();
    for (int o = 512; o > 0; o >>= 1) {
        if (tid < o) sh[tid] += sh[tid + o];
        __syncthreads();
    }
    if (tid == 0) g_diag = sh[0] * INV2V;
}

// ---------------------------------------------------------------------------
// 3) E table
// ---------------------------------------------------------------------------
__global__ void etab_kernel(const float* __restrict__ pos) {
    int p = blockIdx.x * blockDim.x + threadIdx.x;
    if (p >= NB * NPTS) return;
#pragma unroll
    for (int d = 0; d < 3; d++) {
        float theta = TWO_PI_L * (pos[p*3 + d] - HALF_L);
        float s, c;
        sincosf(theta, &s, &c);
        float2 e1 = make_float2(c, -s);           // exp(-i theta)
        float2* E = &g_E[(p*3 + d) * NM];
        E[15] = make_float2(1.0f, 0.0f);
        float2 cur = make_float2(1.0f, 0.0f);
#pragma unroll
        for (int m = 1; m <= 15; m++) {
            cur = cmul(cur, e1);
            E[15 + m] = cur;
            E[15 - m] = make_float2(cur.x, -cur.y);
        }
    }
}

// ---------------------------------------------------------------------------
// 4) Scatter (split over particles). One CTA per (ixh, b, split).
//    Packed f32x2 inner loop: exyz = exy*ez (2 packed), acc_c += q_c*exyz
//    (4 packed). All operand packing hoisted into smem tables per chunk.
// ---------------------------------------------------------------------------
__global__ void __launch_bounds__(256, 3) scatter_kernel(const float* __restrict__ charge) {
    const int ixh   = blockIdx.x;        // 0..15
    const int b     = blockIdx.y;
    const int split = blockIdx.z;
    const int ix    = 15 + ixh;
    const int tid   = threadIdx.x;
    const int iy    = tid >> 3;          // 0..31 (31 inactive)
    const int z0    = (tid & 7) * 4;
    const bool act  = (iy < NM);
    const int jstart = split * JCHUNK;
    const int jend   = jstart + JCHUNK;

    __shared__ u64 sExq[32][32];   // (exy.x, exy.x)
    __shared__ u64 sEyq[32][32];   // (-exy.y, exy.y)
    __shared__ u64 sEz [32][32];   // (ez.x, ez.y)
    __shared__ u64 sEzS[32][32];   // (ez.y, ez.x)
    __shared__ u64 sChD[32][4];    // (q_c, q_c)

    u64 acc[NCH][4];
#pragma unroll
    for (int c = 0; c < NCH; c++)
#pragma unroll
        for (int zl = 0; zl < 4; zl++) acc[c][zl] = 0ull;

    for (int j0 = jstart; j0 < jend; j0 += 32) {
        for (int idx = tid; idx < 32*32; idx += 256) {
            int p = idx >> 5, i = idx & 31;
            int j = j0 + p;
            u64 exq = 0, eyq = 0, ez = 0, ezS = 0;
            if (i < NM && j < jend) {
                int base = (b*NPTS + j) * 3;
                float2 ex  = g_E[(base + 0)*NM + ix];
                float2 ey  = g_E[(base + 1)*NM + i];
                float2 exy = cmul(ex, ey);
                exq = pk(exy.x, exy.x);
                eyq = pk(-exy.y, exy.y);
                float2 z = g_E[(base + 2)*NM + i];
                ez  = pk(z.x, z.y);
                ezS = pk(z.y, z.x);
            }
            sExq[p][i] = exq;
            sEyq[p][i] = eyq;
            sEz [p][i] = ez;
            sEzS[p][i] = ezS;
        }
        if (tid < 32) {
            int j = j0 + tid;
            float4 c4 = make_float4(0.f, 0.f, 0.f, 0.f);
            if (j < jend)
                c4 = *reinterpret_cast<const float4*>(&charge[(b*NPTS + j)*NCH]);
            sChD[tid][0] = pk(c4.x, c4.x);
            sChD[tid][1] = pk(c4.y, c4.y);
            sChD[tid][2] = pk(c4.z, c4.z);
            sChD[tid][3] = pk(c4.w, c4.w);
        }
        __syncthreads();

        if (act) {
#pragma unroll 2
            for (int p = 0; p < 32; p++) {
                u64 exq = sExq[p][iy];
                u64 eyq = sEyq[p][iy];
                u64 q0 = sChD[p][0], q1 = sChD[p][1], q2 = sChD[p][2], q3 = sChD[p][3];
#pragma unroll
                for (int zl = 0; zl < 4; zl++) {
                    u64 ez  = sEz [p][z0 + zl];
                    u64 ezS = sEzS[p][z0 + zl];
                    u64 xyz = ffma2(eyq, ezS, fmul2(exq, ez));  // exy * ez (complex)
                    acc[0][zl] = ffma2(q0, xyz, acc[0][zl]);
                    acc[1][zl] = ffma2(q1, xyz, acc[1][zl]);
                    acc[2][zl] = ffma2(q2, xyz, acc[2][zl]);
                    acc[3][zl] = ffma2(q3, xyz, acc[3][zl]);
                }
            }
        }
        __syncthreads();
    }

    if (act) {
#pragma unroll
        for (int zl = 0; zl < 4; zl++) {
            int z = z0 + zl;
            if (z < NM) {
#pragma unroll
                for (int c = 0; c < NCH; c++) {
                    g_Fp[(((split*NB + b)*NCH + c)*NXH + ixh)*NPLANE + iy*NM + z] =
                        upk(acc[c][zl]);
                }
            }
        }
    }
}

// ---------------------------------------------------------------------------
// 4b) Reduce partials + fold mult (deterministic fixed-order sum)
// ---------------------------------------------------------------------------
__global__ void reduce_kernel() {
    int idx = blockIdx.x * blockDim.x + threadIdx.x;
    const int TOT = NB*NCH*NXH*NPLANE;
    if (idx >= TOT) return;
    float2 s = make_float2(0.0f, 0.0f);
#pragma unroll
    for (int sp = 0; sp < NSPLIT; sp++) {
        float2 v = g_Fp[sp*TOT + idx];
        s.x += v.x; s.y += v.y;
    }
    int rem = idx % NPLANE;
    int ixh = (idx / NPLANE) % NXH;
    float m = g_mult[(15 + ixh)*NPLANE + rem];
    g_F[idx] = make_float2(s.x * m, s.y * m);
}

// ---------------------------------------------------------------------------
// 5) Gather: one CTA per (batch, 8 particles). Packed f32x2:
//    acc pair holds (Σ F.x*e.x, Σ F.y*e.y); horizontal add = Re(F·conj(e)).
// ---------------------------------------------------------------------------
#define NCHP (NCH*NPLANE)   // 3844
__global__ void __launch_bounds__(256, 2) gather_kernel(const float* __restrict__ charge,
                                                        float* __restrict__ out) {
    const int b   = blockIdx.y;
    const int j0  = blockIdx.x * 8;
    const int tid = threadIdx.x;
    const int iy  = tid >> 3;
    const int z0  = (tid & 7) * 4;
    const bool act = (iy < NM);
    const int warp = tid >> 5;
    const int lane = tid & 31;

    __shared__ u64    sF[NCHP + 32];     // one x-plane (+ zero pad for z=31 reads)
    __shared__ float2 pExw[8][NXH];      // weight-folded Ex
    __shared__ float2 pEy[8][32];
    __shared__ u64    pEz[8][32];        // (ez.x, ez.y), slot 31 zero
    __shared__ u64    pEzS[8][32];       // (ez.y, ez.x)
    __shared__ u64    tExq[8][32];       // per-plane (exy.x, exy.x)
    __shared__ u64    tEyq[8][32];       // per-plane (-exy.y, exy.y)
    __shared__ float4 pCh[8];
    __shared__ float  red[8][32];
    __shared__ float  sfin[32];

    // zero the sF pad (stays zero across all planes)
    if (tid < 32) sF[NCHP + tid] = 0ull;

    // particle data
    for (int idx = tid; idx < 8*32; idx += 256) {
        int p = idx >> 5, i = idx & 31;
        int j = j0 + p;
        int base = (b*NPTS + j) * 3;
        float2 vy = make_float2(0.0f, 0.0f);
        u64 ez = 0, ezS = 0;
        if (i < NM) {
            vy = g_E[(base + 1)*NM + i];
            float2 vz = g_E[(base + 2)*NM + i];
            ez  = pk(vz.x, vz.y);
            ezS = pk(vz.y, vz.x);
        }
        pEy[p][i]  = vy;
        pEz[p][i]  = ez;
        pEzS[p][i] = ezS;
    }
    if (tid < 8*NXH) {
        int p = tid >> 4, i = tid & 15;
        int j = j0 + p;
        float2 ex = g_E[((b*NPTS + j)*3 + 0)*NM + 15 + i];
        float w = (i == 0) ? 1.0f : 2.0f;    // Hermitian weight
        pExw[p][i] = make_float2(w*ex.x, w*ex.y);
    }
    if (tid < 8) {
        pCh[tid] = *reinterpret_cast<const float4*>(&charge[(b*NPTS + j0 + tid)*NCH]);
    }

    u64 acc[8][NCH];
#pragma unroll
    for (int p = 0; p < 8; p++)
#pragma unroll
        for (int c = 0; c < NCH; c++) acc[p][c] = 0ull;

    for (int ixh = 0; ixh < NXH; ixh++) {
        __syncthreads();   // protects sF/table reuse (and particle loads on iter 0)
        for (int idx = tid; idx < NCHP; idx += 256) {
            int c = idx / NPLANE;
            int r = idx - c * NPLANE;
            float2 v = g_F[((b*NCH + c)*NXH + ixh)*NPLANE + r];
            sF[idx] = pk(v.x, v.y);
        }
        // per-plane exy packing table (amortized over the 8 threads sharing iy)
        if (tid < 256) {
            int p = tid >> 5, i = tid & 31;
            u64 exq = 0, eyq = 0;
            if (i < NM) {
                float2 exy = cmul(pExw[p][ixh], pEy[p][i]);
                exq = pk(exy.x, exy.x);
                eyq = pk(-exy.y, exy.y);
            }
            tExq[p][i] = exq;
            tEyq[p][i] = eyq;
        }
        __syncthreads();

        if (act) {
            u64 Fr[NCH][4];
#pragma unroll
            for (int c = 0; c < NCH; c++)
#pragma unroll
                for (int zl = 0; zl < 4; zl++)
                    Fr[c][zl] = sF[c*NPLANE + iy*NM + z0 + zl];  // z=31 hits zero pad
#pragma unroll
            for (int p = 0; p < 8; p++) {
                u64 exq = tExq[p][iy];
                u64 eyq = tEyq[p][iy];
#pragma unroll
                for (int zl = 0; zl < 4; zl++) {
                    u64 ez  = pEz [p][z0 + zl];
                    u64 ezS = pEzS[p][z0 + zl];
                    u64 e2  = ffma2(eyq, ezS, fmul2(exq, ez));   // exy*ez
                    acc[p][0] = ffma2(e2, Fr[0][zl], acc[p][0]);
                    acc[p][1] = ffma2(e2, Fr[1][zl], acc[p][1]);
                    acc[p][2] = ffma2(e2, Fr[2][zl], acc[p][2]);
                    acc[p][3] = ffma2(e2, Fr[3][zl], acc[p][3]);
                }
            }
        }
    }
    __syncthreads();

    // horizontal add (Re part) then block reduction
#pragma unroll
    for (int p = 0; p < 8; p++) {
#pragma unroll
        for (int c = 0; c < NCH; c++) {
            float2 f = upk(acc[p][c]);
            float v = f.x + f.y;
#pragma unroll
            for (int off = 16; off > 0; off >>= 1)
                v += __shfl_xor_sync(0xffffffffu, v, off);
            if (lane == 0) red[warp][p*NCH + c] = v;
        }
    }
    __syncthreads();
    if (tid < 32) {
        float s = 0.0f;
#pragma unroll
        for (int w = 0; w < 8; w++) s += red[w][tid];
        sfin[tid] = s;
    }
    __syncthreads();
    if (tid < 8) {
        float diag = g_diag;
        float4 c4 = pCh[tid];
        float e = c4.x * (sfin[tid*NCH + 0]*INV2V - diag)
                + c4.y * (sfin[tid*NCH + 1]*INV2V - diag)
                + c4.z * (sfin[tid*NCH + 2]*INV2V - diag)
                + c4.w * (sfin[tid*NCH + 3]*INV2V - diag);
        out[b*NPTS + j0 + tid] = e;
    }
}

// ---------------------------------------------------------------------------
// Launch
// ---------------------------------------------------------------------------
extern "C" void kernel_launch(void* const* d_in, const int* in_sizes, int n_in,
                              void* d_out, int out_size) {
    const float* pos    = (const float*)d_in[0];
    const float* charge = (const float*)d_in[1];
    const float* shift  = (const float*)d_in[2];
    const float* amp    = (const float*)d_in[3];
    float* out = (float*)d_out;

    mult_kernel<<<(NK + 255)/256, 256>>>(shift, amp);
    diag_kernel<<<1, 1024>>>();
    etab_kernel<<<(NB*NPTS + 127)/128, 128>>>(pos);
    scatter_kernel<<<dim3(NXH, NB, NSPLIT), 256>>>(charge);
    reduce_kernel<<<(NB*NCH*NXH*NPLANE + 255)/256, 256>>>();
    gather_kernel<<<dim3(NPTS/8, NB), 256>>>(charge, out);
}

// round 3
// speedup vs baseline: 1.8830x; 1.8830x over previous
#include <cuda_runtime.h>

// Problem constants
#define NM      31
#define NPLANE  (NM*NM)        // 961
#define NK      (NM*NM*NM)     // 29791
#define NB      8
#define NPTS    3000
#define NCH     4
#define NBW     12
#define NXH     16             // half-space planes nx = 0..15
#define NSPLIT  3
#define JCHUNK  (NPTS/NSPLIT)  // 1000
#define TWO_PI_L 0.628318530717958647692f
#define HALF_L   5.0f
#define INV2V    (1.0f/2000.0f)

typedef unsigned long long u64;

// Padded F tensor: [b][ixh][c][iy:32][z:32], zero-padded at iy=31 / z=31
#define FPAD    (NB*NXH*NCH*32*32)     // 524288 float2 = 4.2 MB

// Scratch (static device globals; allocation-free per harness rules)
__device__ float2 g_E[NB*NPTS*3*NM];                 // [pidx][dim][n]
__device__ float2 g_Fp[NSPLIT*NB*NCH*NXH*NPLANE];    // partial structure factors
__device__ float2 g_F2[FPAD];                        // mult-folded, padded layout
__device__ float  g_mult[NK];
__device__ float  g_diag;

__device__ __forceinline__ float2 cmul(float2 a, float2 b) {
    return make_float2(a.x*b.x - a.y*b.y, a.x*b.y + a.y*b.x);
}
__device__ __forceinline__ u64 pk(float x, float y) {
    u64 r; asm("mov.b64 %0,{%1,%2};" : "=l"(r) : "f"(x), "f"(y)); return r;
}
__device__ __forceinline__ float2 upk(u64 v) {
    float2 f; asm("mov.b64 {%0,%1},%2;" : "=f"(f.x), "=f"(f.y) : "l"(v)); return f;
}
__device__ __forceinline__ u64 swap64(u64 v) {      // (x,y) -> (y,x), register movs
    float2 f = upk(v); return pk(f.y, f.x);
}
__device__ __forceinline__ u64 ffma2(u64 a, u64 b, u64 c) {
    u64 d; asm("fma.rn.f32x2 %0,%1,%2,%3;" : "=l"(d) : "l"(a), "l"(b), "l"(c)); return d;
}
__device__ __forceinline__ u64 fmul2(u64 a, u64 b) {
    u64 d; asm("mul.rn.f32x2 %0,%1,%2;" : "=l"(d) : "l"(a), "l"(b)); return d;
}

// ---------------------------------------------------------------------------
// 1) mult(k)
// ---------------------------------------------------------------------------
__global__ void mult_kernel(const float* __restrict__ shift,
                            const float* __restrict__ amp) {
    int i = blockIdx.x * blockDim.x + threadIdx.x;
    if (i >= NK) return;
    int ix = i / NPLANE;
    int r  = i - ix * NPLANE;
    int iy = r / NM;
    int iz = r - iy * NM;
    float kx = TWO_PI_L * (float)(ix - 15);
    float ky = TWO_PI_L * (float)(iy - 15);
    float kz = TWO_PI_L * (float)(iz - 15);
    float k2 = kx*kx + ky*ky + kz*kz;
    float m = 0.0f;
#pragma unroll
    for (int b = 0; b < NBW; b++) {
        m += amp[b] * __expf(-k2 * __expf(2.0f * shift[b]));
    }
    if (k2 == 0.0f) m = 0.0f;
    g_mult[i] = m;
}

// ---------------------------------------------------------------------------
// 2) diag_sum
// ---------------------------------------------------------------------------
__global__ void diag_kernel() {
    __shared__ float sh[1024];
    int tid = threadIdx.x;
    float s = 0.0f;
    for (int i = tid; i < NK; i += 1024) s += g_mult[i];
    sh[tid] = s;
    __syncthreads();
    for (int o = 512; o > 0; o >>= 1) {
        if (tid < o) sh[tid] += sh[tid + o];
        __syncthreads();
    }
    if (tid == 0) g_diag = sh[0] * INV2V;
}

// ---------------------------------------------------------------------------
// 3) E table
// ---------------------------------------------------------------------------
__global__ void etab_kernel(const float* __restrict__ pos) {
    int p = blockIdx.x * blockDim.x + threadIdx.x;
    if (p >= NB * NPTS) return;
#pragma unroll
    for (int d = 0; d < 3; d++) {
        float theta = TWO_PI_L * (pos[p*3 + d] - HALF_L);
        float s, c;
        sincosf(theta, &s, &c);
        float2 e1 = make_float2(c, -s);           // exp(-i theta)
        float2* E = &g_E[(p*3 + d) * NM];
        E[15] = make_float2(1.0f, 0.0f);
        float2 cur = make_float2(1.0f, 0.0f);
#pragma unroll
        for (int m = 1; m <= 15; m++) {
            cur = cmul(cur, e1);
            E[15 + m] = cur;
            E[15 - m] = make_float2(cur.x, -cur.y);
        }
    }
}

// ---------------------------------------------------------------------------
// 4) Scatter (split over particles). One CTA per (ixh, b, split).
//    Inner loop: 5 LDS.128 + 24 packed FMA per particle; ezS derived by
//    register swap (ALU pipe) instead of a second smem load.
// ---------------------------------------------------------------------------
__global__ void __launch_bounds__(256, 3) scatter_kernel(const float* __restrict__ charge) {
    const int ixh   = blockIdx.x;        // 0..15
    const int b     = blockIdx.y;
    const int split = blockIdx.z;
    const int ix    = 15 + ixh;
    const int tid   = threadIdx.x;
    const int iy    = tid >> 3;          // 0..31 (31 inactive)
    const int zh    = (tid & 7) * 2;     // z-pair index: z0 = zh*2
    const bool act  = (iy < NM);
    const int jstart = split * JCHUNK;
    const int jend   = jstart + JCHUNK;

    __shared__ ulonglong2 sXY[32][32];   // (exq, eyq) per (p, iy)     16 KB
    __shared__ ulonglong2 sEz[32][16];   // z pairs per p               8 KB
    __shared__ ulonglong2 sQ [32][2];    // (q0d,q1d),(q2d,q3d)         1 KB

    u64 acc[NCH][4];
#pragma unroll
    for (int c = 0; c < NCH; c++)
#pragma unroll
        for (int zl = 0; zl < 4; zl++) acc[c][zl] = 0ull;

    u64* sEzU = reinterpret_cast<u64*>(sEz);

    for (int j0 = jstart; j0 < jend; j0 += 32) {
        for (int idx = tid; idx < 32*32; idx += 256) {
            int p = idx >> 5, i = idx & 31;
            int j = j0 + p;
            u64 exq = 0, eyq = 0, ez = 0;
            if (i < NM && j < jend) {
                int base = (b*NPTS + j) * 3;
                float2 ex  = g_E[(base + 0)*NM + ix];
                float2 ey  = g_E[(base + 1)*NM + i];
                float2 exy = cmul(ex, ey);
                exq = pk(exy.x, exy.x);
                eyq = pk(-exy.y, exy.y);
                float2 z = g_E[(base + 2)*NM + i];
                ez = pk(z.x, z.y);
            }
            sXY[p][i] = make_ulonglong2(exq, eyq);
            sEzU[p*32 + i] = ez;
        }
        if (tid < 32) {
            int j = j0 + tid;
            float4 c4 = make_float4(0.f, 0.f, 0.f, 0.f);
            if (j < jend)
                c4 = *reinterpret_cast<const float4*>(&charge[(b*NPTS + j)*NCH]);
            sQ[tid][0] = make_ulonglong2(pk(c4.x, c4.x), pk(c4.y, c4.y));
            sQ[tid][1] = make_ulonglong2(pk(c4.z, c4.z), pk(c4.w, c4.w));
        }
        __syncthreads();

        if (act) {
#pragma unroll 4
            for (int p = 0; p < 32; p++) {
                ulonglong2 xy = sXY[p][iy];             // LDS.128
                ulonglong2 qa = sQ[p][0];               // LDS.128 (broadcast)
                ulonglong2 qb = sQ[p][1];               // LDS.128 (broadcast)
                ulonglong2 ez01 = sEz[p][zh];           // LDS.128
                ulonglong2 ez23 = sEz[p][zh + 1];       // LDS.128
                u64 ezv[4] = {ez01.x, ez01.y, ez23.x, ez23.y};
#pragma unroll
                for (int zl = 0; zl < 4; zl++) {
                    u64 ez  = ezv[zl];
                    u64 xyz = ffma2(xy.y, swap64(ez), fmul2(xy.x, ez));  // exy*ez
                    acc[0][zl] = ffma2(qa.x, xyz, acc[0][zl]);
                    acc[1][zl] = ffma2(qa.y, xyz, acc[1][zl]);
                    acc[2][zl] = ffma2(qb.x, xyz, acc[2][zl]);
                    acc[3][zl] = ffma2(qb.y, xyz, acc[3][zl]);
                }
            }
        }
        __syncthreads();
    }

    if (act) {
        int z0 = zh * 2;
#pragma unroll
        for (int zl = 0; zl < 4; zl++) {
            int z = z0 + zl;
            if (z < NM) {
#pragma unroll
                for (int c = 0; c < NCH; c++) {
                    g_Fp[(((split*NB + b)*NCH + c)*NXH + ixh)*NPLANE + iy*NM + z] =
                        upk(acc[c][zl]);
                }
            }
        }
    }
}

// ---------------------------------------------------------------------------
// 4b) Reduce partials + fold mult into padded layout [b][ixh][c][iy:32][z:32]
// ---------------------------------------------------------------------------
__global__ void reduce_kernel() {
    int idx = blockIdx.x * blockDim.x + threadIdx.x;
    if (idx >= FPAD) return;
    int z   = idx & 31;
    int iy  = (idx >> 5) & 31;
    int c   = (idx >> 10) & 3;
    int ixh = (idx >> 12) & 15;
    int b   = idx >> 16;
    float2 s = make_float2(0.0f, 0.0f);
    if (z < NM && iy < NM) {
        const int TOT = NB*NCH*NXH*NPLANE;
        int src = (((b)*NCH + c)*NXH + ixh)*NPLANE + iy*NM + z;
#pragma unroll
        for (int sp = 0; sp < NSPLIT; sp++) {
            float2 v = g_Fp[sp*TOT + src];
            s.x += v.x; s.y += v.y;
        }
        float m = g_mult[(15 + ixh)*NPLANE + iy*NM + z];
        s.x *= m; s.y *= m;
    }
    g_F2[idx] = s;
}

// ---------------------------------------------------------------------------
// 5) Gather: one CTA per (batch, 8 particles). No F smem staging — each
//    thread's F tile is read directly from the padded L2-resident tensor
//    via coalesced LDG.128 (every element consumed exactly once per CTA,
//    so smem staging added zero reuse).
// ---------------------------------------------------------------------------
__global__ void __launch_bounds__(256, 2) gather_kernel(const float* __restrict__ charge,
                                                        float* __restrict__ out) {
    const int b   = blockIdx.y;
    const int j0  = blockIdx.x * 8;
    const int tid = threadIdx.x;
    const int iy  = tid >> 3;
    const int zh  = (tid & 7) * 2;       // z0 = zh*2
    const bool act = (iy < NM);
    const int warp = tid >> 5;
    const int lane = tid & 31;

    __shared__ float2     pExw[8][NXH];  // weight-folded Ex
    __shared__ float2     pEy[8][32];
    __shared__ ulonglong2 pEz[8][16];    // z pairs, slot z=31 zero
    __shared__ float4     pCh[8];
    __shared__ float      red[8][32];
    __shared__ float      sfin[32];

    u64* pEzU = reinterpret_cast<u64*>(pEz);

    // particle data
    for (int idx = tid; idx < 8*32; idx += 256) {
        int p = idx >> 5, i = idx & 31;
        int j = j0 + p;
        int base = (b*NPTS + j) * 3;
        float2 vy = make_float2(0.0f, 0.0f);
        u64 ez = 0;
        if (i < NM) {
            vy = g_E[(base + 1)*NM + i];
            float2 vz = g_E[(base + 2)*NM + i];
            ez = pk(vz.x, vz.y);
        }
        pEy[p][i] = vy;
        pEzU[p*32 + i] = ez;
    }
    if (tid < 8*NXH) {
        int p = tid >> 4, i = tid & 15;
        int j = j0 + p;
        float2 ex = g_E[((b*NPTS + j)*3 + 0)*NM + 15 + i];
        float w = (i == 0) ? 1.0f : 2.0f;    // Hermitian weight
        pExw[p][i] = make_float2(w*ex.x, w*ex.y);
    }
    if (tid < 8) {
        pCh[tid] = *reinterpret_cast<const float4*>(&charge[(b*NPTS + j0 + tid)*NCH]);
    }
    __syncthreads();

    u64 acc[8][NCH];
#pragma unroll
    for (int p = 0; p < 8; p++)
#pragma unroll
        for (int c = 0; c < NCH; c++) acc[p][c] = 0ull;

    const ulonglong2* Fbase = reinterpret_cast<const ulonglong2*>(g_F2);

    for (int ixh = 0; ixh < NXH; ixh++) {
        if (act) {
            // F tile: 2 coalesced LDG.128 per channel from padded tensor
            u64 Fr[NCH][4];
#pragma unroll
            for (int c = 0; c < NCH; c++) {
                const ulonglong2* fp =
                    Fbase + (((b*NXH + ixh)*NCH + c)*32 + iy)*16 + zh;
                ulonglong2 f0 = fp[0];
                ulonglong2 f1 = fp[1];
                Fr[c][0] = f0.x; Fr[c][1] = f0.y;
                Fr[c][2] = f1.x; Fr[c][3] = f1.y;
            }
#pragma unroll
            for (int p = 0; p < 8; p++) {
                float2 exy = cmul(pExw[p][ixh], pEy[p][iy]);
                u64 exq = pk(exy.x, exy.x);
                u64 eyq = pk(-exy.y, exy.y);
                ulonglong2 ez01 = pEz[p][zh];
                ulonglong2 ez23 = pEz[p][zh + 1];
                u64 ezv[4] = {ez01.x, ez01.y, ez23.x, ez23.y};
#pragma unroll
                for (int zl = 0; zl < 4; zl++) {
                    u64 ez = ezv[zl];
                    u64 e2 = ffma2(eyq, swap64(ez), fmul2(exq, ez));   // exy*ez
                    acc[p][0] = ffma2(e2, Fr[0][zl], acc[p][0]);
                    acc[p][1] = ffma2(e2, Fr[1][zl], acc[p][1]);
                    acc[p][2] = ffma2(e2, Fr[2][zl], acc[p][2]);
                    acc[p][3] = ffma2(e2, Fr[3][zl], acc[p][3]);
                }
            }
        }
    }
    __syncthreads();

    // horizontal add (Re part) then block reduction
#pragma unroll
    for (int p = 0; p < 8; p++) {
#pragma unroll
        for (int c = 0; c < NCH; c++) {
            float2 f = upk(acc[p][c]);
            float v = f.x + f.y;
#pragma unroll
            for (int off = 16; off > 0; off >>= 1)
                v += __shfl_xor_sync(0xffffffffu, v, off);
            if (lane == 0) red[warp][p*NCH + c] = v;
        }
    }
    __syncthreads();
    if (tid < 32) {
        float s = 0.0f;
#pragma unroll
        for (int w = 0; w < 8; w++) s += red[w][tid];
        sfin[tid] = s;
    }
    __syncthreads();
    if (tid < 8) {
        float diag = g_diag;
        float4 c4 = pCh[tid];
        float e = c4.x * (sfin[tid*NCH + 0]*INV2V - diag)
                + c4.y * (sfin[tid*NCH + 1]*INV2V - diag)
                + c4.z * (sfin[tid*NCH + 2]*INV2V - diag)
                + c4.w * (sfin[tid*NCH + 3]*INV2V - diag);
        out[b*NPTS + j0 + tid] = e;
    }
}

// ---------------------------------------------------------------------------
// Launch
// ---------------------------------------------------------------------------
extern "C" void kernel_launch(void* const* d_in, const int* in_sizes, int n_in,
                              void* d_out, int out_size) {
    const float* pos    = (const float*)d_in[0];
    const float* charge = (const float*)d_in[1];
    const float* shift  = (const float*)d_in[2];
    const float* amp    = (const float*)d_in[3];
    float* out = (float*)d_out;

    mult_kernel<<<(NK + 255)/256, 256>>>(shift, amp);
    diag_kernel<<<1, 1024>>>();
    etab_kernel<<<(NB*NPTS + 127)/128, 128>>>(pos);
    scatter_kernel<<<dim3(NXH, NB, NSPLIT), 256>>>(charge);
    reduce_kernel<<<(FPAD + 255)/256, 256>>>();
    gather_kernel<<<dim3(NPTS/8, NB), 256>>>(charge, out);
}

// round 4
// speedup vs baseline: 1.9967x; 1.0604x over previous
#include <cuda_runtime.h>

// Problem constants
#define NM      31
#define NPLANE  (NM*NM)        // 961
#define NK      (NM*NM*NM)     // 29791
#define NB      8
#define NPTS    3000
#define NCH     4
#define NBW     12
#define NXH     16             // half-space planes nx = 0..15
#define NSPLIT  4
#define JCHUNK  (NPTS/NSPLIT)  // 750
#define TWO_PI_L 0.628318530717958647692f
#define HALF_L   5.0f
#define INV2V    (1.0f/2000.0f)

typedef unsigned long long u64;

// Padded F tensor: [b][ixh][c][iy:32][z:32], zero-padded at iy=31 / z=31
#define FPAD    (NB*NXH*NCH*32*32)     // 524288 float2 = 4.2 MB

// Scratch (static device globals; allocation-free per harness rules)
__device__ float2 g_E[NB*NPTS*3*NM];                 // [pidx][dim][n]
__device__ float2 g_Fp[NSPLIT*NB*NCH*NXH*NPLANE];    // partial structure factors
__device__ float2 g_F2[FPAD];                        // mult-folded, padded layout
__device__ float  g_mult[NK];
__device__ float  g_diag;

__device__ __forceinline__ float2 cmul(float2 a, float2 b) {
    return make_float2(a.x*b.x - a.y*b.y, a.x*b.y + a.y*b.x);
}
__device__ __forceinline__ u64 pk(float x, float y) {
    u64 r; asm("mov.b64 %0,{%1,%2};" : "=l"(r) : "f"(x), "f"(y)); return r;
}
__device__ __forceinline__ float2 upk(u64 v) {
    float2 f; asm("mov.b64 {%0,%1},%2;" : "=f"(f.x), "=f"(f.y) : "l"(v)); return f;
}
__device__ __forceinline__ u64 swap64(u64 v) {      // (x,y) -> (y,x), register movs
    float2 f = upk(v); return pk(f.y, f.x);
}
__device__ __forceinline__ u64 ffma2(u64 a, u64 b, u64 c) {
    u64 d; asm("fma.rn.f32x2 %0,%1,%2,%3;" : "=l"(d) : "l"(a), "l"(b), "l"(c)); return d;
}
__device__ __forceinline__ u64 fmul2(u64 a, u64 b) {
    u64 d; asm("mul.rn.f32x2 %0,%1,%2;" : "=l"(d) : "l"(a), "l"(b)); return d;
}

// ---------------------------------------------------------------------------
// 1) mult(k)
// ---------------------------------------------------------------------------
__global__ void mult_kernel(const float* __restrict__ shift,
                            const float* __restrict__ amp) {
    int i = blockIdx.x * blockDim.x + threadIdx.x;
    if (i >= NK) return;
    int ix = i / NPLANE;
    int r  = i - ix * NPLANE;
    int iy = r / NM;
    int iz = r - iy * NM;
    float kx = TWO_PI_L * (float)(ix - 15);
    float ky = TWO_PI_L * (float)(iy - 15);
    float kz = TWO_PI_L * (float)(iz - 15);
    float k2 = kx*kx + ky*ky + kz*kz;
    float m = 0.0f;
#pragma unroll
    for (int b = 0; b < NBW; b++) {
        m += amp[b] * __expf(-k2 * __expf(2.0f * shift[b]));
    }
    if (k2 == 0.0f) m = 0.0f;
    g_mult[i] = m;
}

// ---------------------------------------------------------------------------
// 2) diag_sum
// ---------------------------------------------------------------------------
__global__ void diag_kernel() {
    __shared__ float sh[1024];
    int tid = threadIdx.x;
    float s = 0.0f;
    for (int i = tid; i < NK; i += 1024) s += g_mult[i];
    sh[tid] = s;
    __syncthreads();
    for (int o = 512; o > 0; o >>= 1) {
        if (tid < o) sh[tid] += sh[tid + o];
        __syncthreads();
    }
    if (tid == 0) g_diag = sh[0] * INV2V;
}

// ---------------------------------------------------------------------------
// 3) E table
// ---------------------------------------------------------------------------
__global__ void etab_kernel(const float* __restrict__ pos) {
    int p = blockIdx.x * blockDim.x + threadIdx.x;
    if (p >= NB * NPTS) return;
#pragma unroll
    for (int d = 0; d < 3; d++) {
        float theta = TWO_PI_L * (pos[p*3 + d] - HALF_L);
        float s, c;
        sincosf(theta, &s, &c);
        float2 e1 = make_float2(c, -s);           // exp(-i theta)
        float2* E = &g_E[(p*3 + d) * NM];
        E[15] = make_float2(1.0f, 0.0f);
        float2 cur = make_float2(1.0f, 0.0f);
#pragma unroll
        for (int m = 1; m <= 15; m++) {
            cur = cmul(cur, e1);
            E[15 + m] = cur;
            E[15 - m] = make_float2(cur.x, -cur.y);
        }
    }
}

// ---------------------------------------------------------------------------
// 4) Scatter. One 128-thread CTA per (ixh, b, split); each thread owns a
//    (2 iy) x (4 z) x (4 ch) tile -> 48 packed FMA per 96 smem bytes per
//    particle (was 24 per 80B). ezS swap shared across the 2 iy.
// ---------------------------------------------------------------------------
__global__ void __launch_bounds__(128, 4) scatter_kernel(const float* __restrict__ charge) {
    const int ixh   = blockIdx.x;        // 0..15
    const int b     = blockIdx.y;
    const int split = blockIdx.z;
    const int ix    = 15 + ixh;
    const int tid   = threadIdx.x;
    const int iy0   = (tid >> 3) * 2;    // 0,2,..,30 ; covers iy0, iy0+1
    const int zh    = (tid & 7) * 2;     // z-pair index: z0 = zh*2
    const int jstart = split * JCHUNK;
    const int jend   = jstart + JCHUNK;

    __shared__ ulonglong2 sXY[32][32];   // (exq, eyq) per (p, iy)     16 KB
    __shared__ ulonglong2 sEz[32][16];   // z pairs per p               8 KB
    __shared__ ulonglong2 sQ [32][2];    // (q0d,q1d),(q2d,q3d)         1 KB

    u64 acc[2][NCH][4];
#pragma unroll
    for (int t = 0; t < 2; t++)
#pragma unroll
        for (int c = 0; c < NCH; c++)
#pragma unroll
            for (int zl = 0; zl < 4; zl++) acc[t][c][zl] = 0ull;

    u64* sEzU = reinterpret_cast<u64*>(sEz);

    for (int j0 = jstart; j0 < jend; j0 += 32) {
        for (int idx = tid; idx < 32*32; idx += 128) {
            int p = idx >> 5, i = idx & 31;
            int j = j0 + p;
            u64 exq = 0, eyq = 0, ez = 0;
            if (i < NM && j < jend) {
                int base = (b*NPTS + j) * 3;
                float2 ex  = g_E[(base + 0)*NM + ix];
                float2 ey  = g_E[(base + 1)*NM + i];
                float2 exy = cmul(ex, ey);
                exq = pk(exy.x, exy.x);
                eyq = pk(-exy.y, exy.y);
                float2 z = g_E[(base + 2)*NM + i];
                ez = pk(z.x, z.y);
            }
            sXY[p][i] = make_ulonglong2(exq, eyq);
            sEzU[p*32 + i] = ez;
        }
        if (tid < 32) {
            int j = j0 + tid;
            float4 c4 = make_float4(0.f, 0.f, 0.f, 0.f);
            if (j < jend)
                c4 = *reinterpret_cast<const float4*>(&charge[(b*NPTS + j)*NCH]);
            sQ[tid][0] = make_ulonglong2(pk(c4.x, c4.x), pk(c4.y, c4.y));
            sQ[tid][1] = make_ulonglong2(pk(c4.z, c4.z), pk(c4.w, c4.w));
        }
        __syncthreads();

#pragma unroll 2
        for (int p = 0; p < 32; p++) {
            ulonglong2 xyA = sXY[p][iy0];           // LDS.128
            ulonglong2 xyB = sXY[p][iy0 + 1];       // LDS.128
            ulonglong2 qa = sQ[p][0];               // LDS.128 (broadcast)
            ulonglong2 qb = sQ[p][1];               // LDS.128 (broadcast)
            ulonglong2 ez01 = sEz[p][zh];           // LDS.128
            ulonglong2 ez23 = sEz[p][zh + 1];       // LDS.128
            u64 ezv[4] = {ez01.x, ez01.y, ez23.x, ez23.y};
#pragma unroll
            for (int zl = 0; zl < 4; zl++) {
                u64 ez  = ezv[zl];
                u64 ezS = swap64(ez);               // shared across both iy
                u64 xyzA = ffma2(xyA.y, ezS, fmul2(xyA.x, ez));
                u64 xyzB = ffma2(xyB.y, ezS, fmul2(xyB.x, ez));
                acc[0][0][zl] = ffma2(qa.x, xyzA, acc[0][0][zl]);
                acc[0][1][zl] = ffma2(qa.y, xyzA, acc[0][1][zl]);
                acc[0][2][zl] = ffma2(qb.x, xyzA, acc[0][2][zl]);
                acc[0][3][zl] = ffma2(qb.y, xyzA, acc[0][3][zl]);
                acc[1][0][zl] = ffma2(qa.x, xyzB, acc[1][0][zl]);
                acc[1][1][zl] = ffma2(qa.y, xyzB, acc[1][1][zl]);
                acc[1][2][zl] = ffma2(qb.x, xyzB, acc[1][2][zl]);
                acc[1][3][zl] = ffma2(qb.y, xyzB, acc[1][3][zl]);
            }
        }
        __syncthreads();
    }

    const int z0 = zh * 2;
#pragma unroll
    for (int t = 0; t < 2; t++) {
        int iy = iy0 + t;
        if (iy < NM) {
#pragma unroll
            for (int zl = 0; zl < 4; zl++) {
                int z = z0 + zl;
                if (z < NM) {
#pragma unroll
                    for (int c = 0; c < NCH; c++) {
                        g_Fp[(((split*NB + b)*NCH + c)*NXH + ixh)*NPLANE + iy*NM + z] =
                            upk(acc[t][c][zl]);
                    }
                }
            }
        }
    }
}

// ---------------------------------------------------------------------------
// 4b) Reduce partials + fold mult into padded layout [b][ixh][c][iy:32][z:32]
// ---------------------------------------------------------------------------
__global__ void reduce_kernel() {
    int idx = blockIdx.x * blockDim.x + threadIdx.x;
    if (idx >= FPAD) return;
    int z   = idx & 31;
    int iy  = (idx >> 5) & 31;
    int c   = (idx >> 10) & 3;
    int ixh = (idx >> 12) & 15;
    int b   = idx >> 16;
    float2 s = make_float2(0.0f, 0.0f);
    if (z < NM && iy < NM) {
        const int TOT = NB*NCH*NXH*NPLANE;
        int src = (((b)*NCH + c)*NXH + ixh)*NPLANE + iy*NM + z;
#pragma unroll
        for (int sp = 0; sp < NSPLIT; sp++) {
            float2 v = g_Fp[sp*TOT + src];
            s.x += v.x; s.y += v.y;
        }
        float m = g_mult[(15 + ixh)*NPLANE + iy*NM + z];
        s.x *= m; s.y *= m;
    }
    g_F2[idx] = s;
}

// ---------------------------------------------------------------------------
// 5) Gather: one CTA per (batch, 8 particles). F read directly from padded
//    L2-resident tensor via coalesced LDG.128 (no smem staging).
// ---------------------------------------------------------------------------
__global__ void __launch_bounds__(256, 2) gather_kernel(const float* __restrict__ charge,
                                                        float* __restrict__ out) {
    const int b   = blockIdx.y;
    const int j0  = blockIdx.x * 8;
    const int tid = threadIdx.x;
    const int iy  = tid >> 3;
    const int zh  = (tid & 7) * 2;       // z0 = zh*2
    const bool act = (iy < NM);
    const int warp = tid >> 5;
    const int lane = tid & 31;

    __shared__ float2     pExw[8][NXH];  // weight-folded Ex
    __shared__ float2     pEy[8][32];
    __shared__ ulonglong2 pEz[8][16];    // z pairs, slot z=31 zero
    __shared__ float4     pCh[8];
    __shared__ float      red[8][32];
    __shared__ float      sfin[32];

    u64* pEzU = reinterpret_cast<u64*>(pEz);

    // particle data
    for (int idx = tid; idx < 8*32; idx += 256) {
        int p = idx >> 5, i = idx & 31;
        int j = j0 + p;
        int base = (b*NPTS + j) * 3;
        float2 vy = make_float2(0.0f, 0.0f);
        u64 ez = 0;
        if (i < NM) {
            vy = g_E[(base + 1)*NM + i];
            float2 vz = g_E[(base + 2)*NM + i];
            ez = pk(vz.x, vz.y);
        }
        pEy[p][i] = vy;
        pEzU[p*32 + i] = ez;
    }
    if (tid < 8*NXH) {
        int p = tid >> 4, i = tid & 15;
        int j = j0 + p;
        float2 ex = g_E[((b*NPTS + j)*3 + 0)*NM + 15 + i];
        float w = (i == 0) ? 1.0f : 2.0f;    // Hermitian weight
        pExw[p][i] = make_float2(w*ex.x, w*ex.y);
    }
    if (tid < 8) {
        pCh[tid] = *reinterpret_cast<const float4*>(&charge[(b*NPTS + j0 + tid)*NCH]);
    }
    __syncthreads();

    u64 acc[8][NCH];
#pragma unroll
    for (int p = 0; p < 8; p++)
#pragma unroll
        for (int c = 0; c < NCH; c++) acc[p][c] = 0ull;

    const ulonglong2* Fbase = reinterpret_cast<const ulonglong2*>(g_F2);

    for (int ixh = 0; ixh < NXH; ixh++) {
        if (act) {
            u64 Fr[NCH][4];
#pragma unroll
            for (int c = 0; c < NCH; c++) {
                const ulonglong2* fp =
                    Fbase + (((b*NXH + ixh)*NCH + c)*32 + iy)*16 + zh;
                ulonglong2 f0 = fp[0];
                ulonglong2 f1 = fp[1];
                Fr[c][0] = f0.x; Fr[c][1] = f0.y;
                Fr[c][2] = f1.x; Fr[c][3] = f1.y;
            }
#pragma unroll
            for (int p = 0; p < 8; p++) {
                float2 exy = cmul(pExw[p][ixh], pEy[p][iy]);
                u64 exq = pk(exy.x, exy.x);
                u64 eyq = pk(-exy.y, exy.y);
                ulonglong2 ez01 = pEz[p][zh];
                ulonglong2 ez23 = pEz[p][zh + 1];
                u64 ezv[4] = {ez01.x, ez01.y, ez23.x, ez23.y};
#pragma unroll
                for (int zl = 0; zl < 4; zl++) {
                    u64 ez = ezv[zl];
                    u64 e2 = ffma2(eyq, swap64(ez), fmul2(exq, ez));   // exy*ez
                    acc[p][0] = ffma2(e2, Fr[0][zl], acc[p][0]);
                    acc[p][1] = ffma2(e2, Fr[1][zl], acc[p][1]);
                    acc[p][2] = ffma2(e2, Fr[2][zl], acc[p][2]);
                    acc[p][3] = ffma2(e2, Fr[3][zl], acc[p][3]);
                }
            }
        }
    }
    __syncthreads();

    // horizontal add (Re part) then block reduction
#pragma unroll
    for (int p = 0; p < 8; p++) {
#pragma unroll
        for (int c = 0; c < NCH; c++) {
            float2 f = upk(acc[p][c]);
            float v = f.x + f.y;
#pragma unroll
            for (int off = 16; off > 0; off >>= 1)
                v += __shfl_xor_sync(0xffffffffu, v, off);
            if (lane == 0) red[warp][p*NCH + c] = v;
        }
    }
    __syncthreads();
    if (tid < 32) {
        float s = 0.0f;
#pragma unroll
        for (int w = 0; w < 8; w++) s += red[w][tid];
        sfin[tid] = s;
    }
    __syncthreads();
    if (tid < 8) {
        float diag = g_diag;
        float4 c4 = pCh[tid];
        float e = c4.x * (sfin[tid*NCH + 0]*INV2V - diag)
                + c4.y * (sfin[tid*NCH + 1]*INV2V - diag)
                + c4.z * (sfin[tid*NCH + 2]*INV2V - diag)
                + c4.w * (sfin[tid*NCH + 3]*INV2V - diag);
        out[b*NPTS + j0 + tid] = e;
    }
}

// ---------------------------------------------------------------------------
// Launch
// ---------------------------------------------------------------------------
extern "C" void kernel_launch(void* const* d_in, const int* in_sizes, int n_in,
                              void* d_out, int out_size) {
    const float* pos    = (const float*)d_in[0];
    const float* charge = (const float*)d_in[1];
    const float* shift  = (const float*)d_in[2];
    const float* amp    = (const float*)d_in[3];
    float* out = (float*)d_out;

    mult_kernel<<<(NK + 255)/256, 256>>>(shift, amp);
    diag_kernel<<<1, 1024>>>();
    etab_kernel<<<(NB*NPTS + 127)/128, 128>>>(pos);
    scatter_kernel<<<dim3(NXH, NB, NSPLIT), 128>>>(charge);
    reduce_kernel<<<(FPAD + 255)/256, 256>>>();
    gather_kernel<<<dim3(NPTS/8, NB), 256>>>(charge, out);
}